// round 6
// baseline (speedup 1.0000x reference)
#include <cuda_runtime.h>
#include <math.h>

#define T_TOK 524288
#define D_DIM 256
#define N_SEG 8192
#define PGRID 888   // 148 SM x 6 blocks

__device__ __align__(16) float g_mean[N_SEG * D_DIM];
__device__ __align__(16) float g_tg[N_SEG * D_DIM];
__device__ int g_segstart[N_SEG + 1];

// ---------------------------------------------------------------------------
// Pass 0: segment boundaries from sorted obj.
// ---------------------------------------------------------------------------
__global__ void k_bounds(const int* __restrict__ obj) {
    int t = blockIdx.x * blockDim.x + threadIdx.x;
    if (t >= T_TOK) return;
    if (t == 0) {
        int v0 = obj[0];
        for (int j = 0; j <= v0; ++j) g_segstart[j] = 0;
        int vl = obj[T_TOK - 1];
        for (int j = vl + 1; j <= N_SEG; ++j) g_segstart[j] = T_TOK;
    } else {
        int p = obj[t - 1], c = obj[t];
        for (int j = p + 1; j <= c; ++j) g_segstart[j] = t;
    }
}

// ---------------------------------------------------------------------------
// Pass 1: per-segment mean. PERSISTENT blocks: each block loops over segments
// bid, bid+PGRID, ... Thread owns float4 column (tid&63)*4 of row-group tid>>6.
// ---------------------------------------------------------------------------
__global__ void __launch_bounds__(256, 6)
k_segmean(const float* __restrict__ emb) {
    int tid = threadIdx.x;
    __shared__ __align__(16) float red[4][256];
    int r = tid >> 6;
    int c4 = (tid & 63) * 4;
    const float4* base = (const float4*)emb + (c4 >> 2);

    for (int n = blockIdx.x; n < N_SEG; n += PGRID) {
        int s = g_segstart[n], e = g_segstart[n + 1];
        float4 acc = make_float4(0.f, 0.f, 0.f, 0.f);
#pragma unroll 4
        for (int t = s + r; t < e; t += 4) {
            float4 v = __ldcs(base + (size_t)t * 64);
            acc.x += v.x; acc.y += v.y; acc.z += v.z; acc.w += v.w;
        }
        *(float4*)&red[r][c4] = acc;
        __syncthreads();
        float sum = red[0][tid] + red[1][tid] + red[2][tid] + red[3][tid];
        g_mean[(size_t)n * D_DIM + tid] = sum / fmaxf((float)(e - s), 1.f);
        __syncthreads();   // red reused next segment
    }
}

// ---------------------------------------------------------------------------
// Pass 2: g_tg = tanh(g_mean @ W). Tiled SGEMM, BM=128, BN=64, BK=16,
// 256 threads, 8x4 register tile.
// ---------------------------------------------------------------------------
__global__ void k_gemm_tanh(const float* __restrict__ W) {
    __shared__ __align__(16) float As[16][128];
    __shared__ __align__(16) float Bs[16][64];
    int tid = threadIdx.x;
    int tx = tid & 15, ty = tid >> 4;          // tx: N (4 cols), ty: M (8 rows)
    int bm = blockIdx.x * 128, bn = blockIdx.y * 64;

    int br  = tid >> 4;          // B tile k-row 0..15
    int bc4 = (tid & 15) * 4;    // B tile col start

    float acc[8][4] = {};
    for (int k0 = 0; k0 < 256; k0 += 16) {
        // A tile: 128 rows x 16 k = 512 float4 slots; 2 per thread.
#pragma unroll
        for (int q = 0; q < 2; ++q) {
            int slot = tid * 2 + q;
            int row = slot >> 2;
            int kq  = (slot & 3) * 4;
            float4 av = *(const float4*)(g_mean + (size_t)(bm + row) * 256 + k0 + kq);
            As[kq + 0][row] = av.x;
            As[kq + 1][row] = av.y;
            As[kq + 2][row] = av.z;
            As[kq + 3][row] = av.w;
        }
        float4 bv = *(const float4*)(W + (size_t)(k0 + br) * 256 + bn + bc4);
        *(float4*)&Bs[br][bc4] = bv;
        __syncthreads();
#pragma unroll
        for (int k = 0; k < 16; ++k) {
            float a[8], b[4];
            *(float4*)&a[0] = *(const float4*)&As[k][ty * 8];
            *(float4*)&a[4] = *(const float4*)&As[k][ty * 8 + 4];
            *(float4*)b = *(const float4*)&Bs[k][tx * 4];
#pragma unroll
            for (int i = 0; i < 8; ++i)
#pragma unroll
                for (int j = 0; j < 4; ++j)
                    acc[i][j] += a[i] * b[j];
        }
        __syncthreads();
    }
#pragma unroll
    for (int i = 0; i < 8; ++i) {
        float4 o;
        o.x = tanhf(acc[i][0]);
        o.y = tanhf(acc[i][1]);
        o.z = tanhf(acc[i][2]);
        o.w = tanhf(acc[i][3]);
        *(float4*)(g_tg + (size_t)(bm + ty * 8 + i) * 256 + bn + tx * 4) = o;
    }
}

// ---------------------------------------------------------------------------
// Pass 3 (fused): scores + weighted segment sum + broadcast. PERSISTENT
// blocks; warp processes two tokens per iteration.
// ---------------------------------------------------------------------------
__global__ void __launch_bounds__(256, 6)
k_score_rep_bcast(const float* __restrict__ emb, float* __restrict__ out) {
    int tid = threadIdx.x;
    __shared__ __align__(16) float stg[256];
    __shared__ __align__(16) float srep[256];
    int lane = tid & 31, w = tid >> 5;
    const float4* base = (const float4*)emb + lane * 2;
    int c = tid & 63;
    int r = tid >> 6;
    float4* ob = (float4*)out + c;

    for (int n = blockIdx.x; n < N_SEG; n += PGRID) {
        int s = g_segstart[n], e = g_segstart[n + 1];
        stg[tid]  = g_tg[(size_t)n * 256 + tid];
        srep[tid] = 0.f;
        __syncthreads();

        float4 tga = *(const float4*)&stg[lane * 8];
        float4 tgb = *(const float4*)&stg[lane * 8 + 4];
        float acc[8] = {0.f,0.f,0.f,0.f,0.f,0.f,0.f,0.f};

        int t = s + 2 * w;
        for (; t + 1 < e; t += 16) {
            float4 a0 = __ldcs(base + (size_t)(t + 0) * 64);
            float4 b0 = __ldcs(base + (size_t)(t + 0) * 64 + 1);
            float4 a1 = __ldcs(base + (size_t)(t + 1) * 64);
            float4 b1 = __ldcs(base + (size_t)(t + 1) * 64 + 1);
            float d0 = a0.x*tga.x + a0.y*tga.y + a0.z*tga.z + a0.w*tga.w
                     + b0.x*tgb.x + b0.y*tgb.y + b0.z*tgb.z + b0.w*tgb.w;
            float d1 = a1.x*tga.x + a1.y*tga.y + a1.z*tga.z + a1.w*tga.w
                     + b1.x*tgb.x + b1.y*tgb.y + b1.z*tgb.z + b1.w*tgb.w;
#pragma unroll
            for (int off = 16; off; off >>= 1) {
                d0 += __shfl_xor_sync(0xffffffffu, d0, off);
                d1 += __shfl_xor_sync(0xffffffffu, d1, off);
            }
            float s0 = 1.f / (1.f + __expf(-d0));
            float s1 = 1.f / (1.f + __expf(-d1));
            acc[0] += a0.x*s0 + a1.x*s1;
            acc[1] += a0.y*s0 + a1.y*s1;
            acc[2] += a0.z*s0 + a1.z*s1;
            acc[3] += a0.w*s0 + a1.w*s1;
            acc[4] += b0.x*s0 + b1.x*s1;
            acc[5] += b0.y*s0 + b1.y*s1;
            acc[6] += b0.z*s0 + b1.z*s1;
            acc[7] += b0.w*s0 + b1.w*s1;
        }
        if (t < e) {
            float4 a0 = __ldcs(base + (size_t)t * 64);
            float4 b0 = __ldcs(base + (size_t)t * 64 + 1);
            float d0 = a0.x*tga.x + a0.y*tga.y + a0.z*tga.z + a0.w*tga.w
                     + b0.x*tgb.x + b0.y*tgb.y + b0.z*tgb.z + b0.w*tgb.w;
#pragma unroll
            for (int off = 16; off; off >>= 1)
                d0 += __shfl_xor_sync(0xffffffffu, d0, off);
            float s0 = 1.f / (1.f + __expf(-d0));
            acc[0] += a0.x*s0; acc[1] += a0.y*s0;
            acc[2] += a0.z*s0; acc[3] += a0.w*s0;
            acc[4] += b0.x*s0; acc[5] += b0.y*s0;
            acc[6] += b0.z*s0; acc[7] += b0.w*s0;
        }
#pragma unroll
        for (int i = 0; i < 8; ++i)
            atomicAdd(&srep[lane * 8 + i], acc[i]);
        __syncthreads();

        float4 rv = *(const float4*)&srep[c * 4];
        for (int tt = s + r; tt < e; tt += 4)
            __stcs(ob + (size_t)tt * 64, rv);
        __syncthreads();   // stg/srep reused next segment
    }
}

extern "C" void kernel_launch(void* const* d_in, const int* in_sizes, int n_in,
                              void* d_out, int out_size) {
    const float* emb = (const float*)d_in[0];
    const float* W   = (const float*)d_in[1];
    const int*   obj = (const int*)d_in[2];
    float*       out = (float*)d_out;

    k_bounds<<<(T_TOK + 255) / 256, 256>>>(obj);
    k_segmean<<<PGRID, 256>>>(emb);
    k_gemm_tanh<<<dim3(N_SEG / 128, D_DIM / 64), 256>>>(W);
    k_score_rep_bcast<<<PGRID, 256>>>(emb, out);
}

// round 7
// speedup vs baseline: 1.0438x; 1.0438x over previous
#include <cuda_runtime.h>
#include <math.h>

#define T_TOK 524288
#define D_DIM 256
#define N_SEG 8192

__device__ __align__(16) float g_mean[N_SEG * D_DIM];
__device__ __align__(16) float g_tg[N_SEG * D_DIM];
__device__ int g_segstart[N_SEG + 1];

// ---------------------------------------------------------------------------
// Pass 0: segment boundaries from sorted obj.
// ---------------------------------------------------------------------------
__global__ void k_bounds(const int* __restrict__ obj) {
    int t = blockIdx.x * blockDim.x + threadIdx.x;
    if (t >= T_TOK) return;
    if (t == 0) {
        int v0 = obj[0];
        for (int j = 0; j <= v0; ++j) g_segstart[j] = 0;
        int vl = obj[T_TOK - 1];
        for (int j = vl + 1; j <= N_SEG; ++j) g_segstart[j] = T_TOK;
    } else {
        int p = obj[t - 1], c = obj[t];
        for (int j = p + 1; j <= c; ++j) g_segstart[j] = t;
    }
}

// ---------------------------------------------------------------------------
// Pass 1: per-segment mean. One block per segment; thread owns float4 column
// (tid&63)*4 of row-group tid>>6; rows stride 4. 8 blocks/SM (32-reg cap).
// ---------------------------------------------------------------------------
__global__ void __launch_bounds__(256, 8)
k_segmean(const float* __restrict__ emb) {
    int n = blockIdx.x, tid = threadIdx.x;
    __shared__ __align__(16) float red[4][256];
    int s = g_segstart[n], e = g_segstart[n + 1];

    int r = tid >> 6;
    int c4 = (tid & 63) * 4;
    const float4* base = (const float4*)emb + (c4 >> 2);

    float4 acc = make_float4(0.f, 0.f, 0.f, 0.f);
#pragma unroll 4
    for (int t = s + r; t < e; t += 4) {
        float4 v = __ldcs(base + (size_t)t * 64);
        acc.x += v.x; acc.y += v.y; acc.z += v.z; acc.w += v.w;
    }
    *(float4*)&red[r][c4] = acc;
    __syncthreads();

    float sum = red[0][tid] + red[1][tid] + red[2][tid] + red[3][tid];
    g_mean[(size_t)n * D_DIM + tid] = sum / fmaxf((float)(e - s), 1.f);
}

// ---------------------------------------------------------------------------
// Pass 2: g_tg = tanh(g_mean @ W). Tiled SGEMM, BM=128, BN=64, BK=16,
// 256 threads, 8x4 register tile.
// ---------------------------------------------------------------------------
__global__ void k_gemm_tanh(const float* __restrict__ W) {
    __shared__ __align__(16) float As[16][128];
    __shared__ __align__(16) float Bs[16][64];
    int tid = threadIdx.x;
    int tx = tid & 15, ty = tid >> 4;
    int bm = blockIdx.x * 128, bn = blockIdx.y * 64;

    int br  = tid >> 4;
    int bc4 = (tid & 15) * 4;

    float acc[8][4] = {};
    for (int k0 = 0; k0 < 256; k0 += 16) {
#pragma unroll
        for (int q = 0; q < 2; ++q) {
            int slot = tid * 2 + q;
            int row = slot >> 2;
            int kq  = (slot & 3) * 4;
            float4 av = *(const float4*)(g_mean + (size_t)(bm + row) * 256 + k0 + kq);
            As[kq + 0][row] = av.x;
            As[kq + 1][row] = av.y;
            As[kq + 2][row] = av.z;
            As[kq + 3][row] = av.w;
        }
        float4 bv = *(const float4*)(W + (size_t)(k0 + br) * 256 + bn + bc4);
        *(float4*)&Bs[br][bc4] = bv;
        __syncthreads();
#pragma unroll
        for (int k = 0; k < 16; ++k) {
            float a[8], b[4];
            *(float4*)&a[0] = *(const float4*)&As[k][ty * 8];
            *(float4*)&a[4] = *(const float4*)&As[k][ty * 8 + 4];
            *(float4*)b = *(const float4*)&Bs[k][tx * 4];
#pragma unroll
            for (int i = 0; i < 8; ++i)
#pragma unroll
                for (int j = 0; j < 4; ++j)
                    acc[i][j] += a[i] * b[j];
        }
        __syncthreads();
    }
#pragma unroll
    for (int i = 0; i < 8; ++i) {
        float4 o;
        o.x = tanhf(acc[i][0]);
        o.y = tanhf(acc[i][1]);
        o.z = tanhf(acc[i][2]);
        o.w = tanhf(acc[i][3]);
        *(float4*)(g_tg + (size_t)(bm + ty * 8 + i) * 256 + bn + tx * 4) = o;
    }
}

// ---------------------------------------------------------------------------
// Pass 3 (fused): scores + weighted segment sum + broadcast. One block per
// segment; warp processes two tokens per iteration.
// ---------------------------------------------------------------------------
__global__ void __launch_bounds__(256, 6)
k_score_rep_bcast(const float* __restrict__ emb, float* __restrict__ out) {
    int n = blockIdx.x, tid = threadIdx.x;
    __shared__ __align__(16) float stg[256];
    __shared__ __align__(16) float srep[256];
    int s = g_segstart[n], e = g_segstart[n + 1];
    stg[tid]  = g_tg[(size_t)n * 256 + tid];
    srep[tid] = 0.f;
    __syncthreads();
    int lane = tid & 31, w = tid >> 5;

    float4 tga = *(const float4*)&stg[lane * 8];
    float4 tgb = *(const float4*)&stg[lane * 8 + 4];
    float acc[8] = {0.f,0.f,0.f,0.f,0.f,0.f,0.f,0.f};

    const float4* base = (const float4*)emb + lane * 2;

    int t = s + 2 * w;
    for (; t + 1 < e; t += 16) {
        float4 a0 = __ldcs(base + (size_t)(t + 0) * 64);
        float4 b0 = __ldcs(base + (size_t)(t + 0) * 64 + 1);
        float4 a1 = __ldcs(base + (size_t)(t + 1) * 64);
        float4 b1 = __ldcs(base + (size_t)(t + 1) * 64 + 1);
        float d0 = a0.x*tga.x + a0.y*tga.y + a0.z*tga.z + a0.w*tga.w
                 + b0.x*tgb.x + b0.y*tgb.y + b0.z*tgb.z + b0.w*tgb.w;
        float d1 = a1.x*tga.x + a1.y*tga.y + a1.z*tga.z + a1.w*tga.w
                 + b1.x*tgb.x + b1.y*tgb.y + b1.z*tgb.z + b1.w*tgb.w;
#pragma unroll
        for (int off = 16; off; off >>= 1) {
            d0 += __shfl_xor_sync(0xffffffffu, d0, off);
            d1 += __shfl_xor_sync(0xffffffffu, d1, off);
        }
        float s0 = 1.f / (1.f + __expf(-d0));
        float s1 = 1.f / (1.f + __expf(-d1));
        acc[0] += a0.x*s0 + a1.x*s1;
        acc[1] += a0.y*s0 + a1.y*s1;
        acc[2] += a0.z*s0 + a1.z*s1;
        acc[3] += a0.w*s0 + a1.w*s1;
        acc[4] += b0.x*s0 + b1.x*s1;
        acc[5] += b0.y*s0 + b1.y*s1;
        acc[6] += b0.z*s0 + b1.z*s1;
        acc[7] += b0.w*s0 + b1.w*s1;
    }
    if (t < e) {
        float4 a0 = __ldcs(base + (size_t)t * 64);
        float4 b0 = __ldcs(base + (size_t)t * 64 + 1);
        float d0 = a0.x*tga.x + a0.y*tga.y + a0.z*tga.z + a0.w*tga.w
                 + b0.x*tgb.x + b0.y*tgb.y + b0.z*tgb.z + b0.w*tgb.w;
#pragma unroll
        for (int off = 16; off; off >>= 1)
            d0 += __shfl_xor_sync(0xffffffffu, d0, off);
        float s0 = 1.f / (1.f + __expf(-d0));
        acc[0] += a0.x*s0; acc[1] += a0.y*s0;
        acc[2] += a0.z*s0; acc[3] += a0.w*s0;
        acc[4] += b0.x*s0; acc[5] += b0.y*s0;
        acc[6] += b0.z*s0; acc[7] += b0.w*s0;
    }
#pragma unroll
    for (int i = 0; i < 8; ++i)
        atomicAdd(&srep[lane * 8 + i], acc[i]);
    __syncthreads();

    int c = tid & 63;
    int r = tid >> 6;
    float4 rv = *(const float4*)&srep[c * 4];
    float4* ob = (float4*)out + c;
    for (int tt = s + r; tt < e; tt += 4)
        __stcs(ob + (size_t)tt * 64, rv);
}

extern "C" void kernel_launch(void* const* d_in, const int* in_sizes, int n_in,
                              void* d_out, int out_size) {
    const float* emb = (const float*)d_in[0];
    const float* W   = (const float*)d_in[1];
    const int*   obj = (const int*)d_in[2];
    float*       out = (float*)d_out;

    k_bounds<<<(T_TOK + 255) / 256, 256>>>(obj);
    k_segmean<<<N_SEG, 256>>>(emb);
    k_gemm_tanh<<<dim3(N_SEG / 128, D_DIM / 64), 256>>>(W);
    k_score_rep_bcast<<<N_SEG, 256>>>(emb, out);
}

// round 8
// speedup vs baseline: 1.0765x; 1.0313x over previous
#include <cuda_runtime.h>
#include <math.h>

#define T_TOK 524288
#define D_DIM 256
#define N_SEG 8192

__device__ __align__(16) float g_mean[N_SEG * D_DIM];
__device__ __align__(16) float g_tg[N_SEG * D_DIM];
__device__ int g_segstart[N_SEG + 1];

// ---------------------------------------------------------------------------
// Pass 0: segment boundaries from sorted obj.
// ---------------------------------------------------------------------------
__global__ void k_bounds(const int* __restrict__ obj) {
    int t = blockIdx.x * blockDim.x + threadIdx.x;
    if (t >= T_TOK) return;
    if (t == 0) {
        int v0 = obj[0];
        for (int j = 0; j <= v0; ++j) g_segstart[j] = 0;
        int vl = obj[T_TOK - 1];
        for (int j = vl + 1; j <= N_SEG; ++j) g_segstart[j] = T_TOK;
    } else {
        int p = obj[t - 1], c = obj[t];
        for (int j = p + 1; j <= c; ++j) g_segstart[j] = t;
    }
}

// ---------------------------------------------------------------------------
// Pass 1: per-segment mean. One 512-thread block per segment; thread owns
// float4 column (tid&63)*4 of row-group tid>>6 (8 groups, stride 8).
// ---------------------------------------------------------------------------
__global__ void __launch_bounds__(512)
k_segmean(const float* __restrict__ emb) {
    int n = blockIdx.x, tid = threadIdx.x;
    __shared__ __align__(16) float red[8][256];
    int s = g_segstart[n], e = g_segstart[n + 1];

    int r = tid >> 6;            // 0..7
    int c4 = (tid & 63) * 4;
    const float4* base = (const float4*)emb + (c4 >> 2);

    float4 acc = make_float4(0.f, 0.f, 0.f, 0.f);
#pragma unroll 4
    for (int t = s + r; t < e; t += 8) {
        float4 v = __ldcs(base + (size_t)t * 64);
        acc.x += v.x; acc.y += v.y; acc.z += v.z; acc.w += v.w;
    }
    *(float4*)&red[r][c4] = acc;
    __syncthreads();

    if (tid < 256) {
        float sum = 0.f;
#pragma unroll
        for (int j = 0; j < 8; ++j) sum += red[j][tid];
        g_mean[(size_t)n * D_DIM + tid] = sum / fmaxf((float)(e - s), 1.f);
    }
}

// ---------------------------------------------------------------------------
// Pass 2: g_tg = tanh(g_mean @ W). Tiled SGEMM, BM=128, BN=64, BK=16,
// 256 threads, 8x4 register tile.
// ---------------------------------------------------------------------------
__global__ void k_gemm_tanh(const float* __restrict__ W) {
    __shared__ __align__(16) float As[16][128];
    __shared__ __align__(16) float Bs[16][64];
    int tid = threadIdx.x;
    int tx = tid & 15, ty = tid >> 4;
    int bm = blockIdx.x * 128, bn = blockIdx.y * 64;

    int br  = tid >> 4;
    int bc4 = (tid & 15) * 4;

    float acc[8][4] = {};
    for (int k0 = 0; k0 < 256; k0 += 16) {
#pragma unroll
        for (int q = 0; q < 2; ++q) {
            int slot = tid * 2 + q;
            int row = slot >> 2;
            int kq  = (slot & 3) * 4;
            float4 av = *(const float4*)(g_mean + (size_t)(bm + row) * 256 + k0 + kq);
            As[kq + 0][row] = av.x;
            As[kq + 1][row] = av.y;
            As[kq + 2][row] = av.z;
            As[kq + 3][row] = av.w;
        }
        float4 bv = *(const float4*)(W + (size_t)(k0 + br) * 256 + bn + bc4);
        *(float4*)&Bs[br][bc4] = bv;
        __syncthreads();
#pragma unroll
        for (int k = 0; k < 16; ++k) {
            float a[8], b[4];
            *(float4*)&a[0] = *(const float4*)&As[k][ty * 8];
            *(float4*)&a[4] = *(const float4*)&As[k][ty * 8 + 4];
            *(float4*)b = *(const float4*)&Bs[k][tx * 4];
#pragma unroll
            for (int i = 0; i < 8; ++i)
#pragma unroll
                for (int j = 0; j < 4; ++j)
                    acc[i][j] += a[i] * b[j];
        }
        __syncthreads();
    }
#pragma unroll
    for (int i = 0; i < 8; ++i) {
        float4 o;
        o.x = tanhf(acc[i][0]);
        o.y = tanhf(acc[i][1]);
        o.z = tanhf(acc[i][2]);
        o.w = tanhf(acc[i][3]);
        *(float4*)(g_tg + (size_t)(bm + ty * 8 + i) * 256 + bn + tx * 4) = o;
    }
}

// ---------------------------------------------------------------------------
// Pass 3 (fused): scores + weighted segment sum + broadcast. One block per
// segment; warp processes two tokens per iteration. Per-warp smem rows +
// tree combine instead of bank-conflicted shared atomics.
// ---------------------------------------------------------------------------
__global__ void __launch_bounds__(256, 6)
k_score_rep_bcast(const float* __restrict__ emb, float* __restrict__ out) {
    int n = blockIdx.x, tid = threadIdx.x;
    __shared__ __align__(16) float stg[256];
    __shared__ __align__(16) float redw[8][256];
    __shared__ __align__(16) float srep[256];
    int s = g_segstart[n], e = g_segstart[n + 1];
    stg[tid] = g_tg[(size_t)n * 256 + tid];
    __syncthreads();
    int lane = tid & 31, w = tid >> 5;

    float4 tga = *(const float4*)&stg[lane * 8];
    float4 tgb = *(const float4*)&stg[lane * 8 + 4];
    float4 accA = make_float4(0.f, 0.f, 0.f, 0.f);
    float4 accB = make_float4(0.f, 0.f, 0.f, 0.f);

    const float4* base = (const float4*)emb + lane * 2;

    int t = s + 2 * w;
    for (; t + 1 < e; t += 16) {
        float4 a0 = __ldcs(base + (size_t)(t + 0) * 64);
        float4 b0 = __ldcs(base + (size_t)(t + 0) * 64 + 1);
        float4 a1 = __ldcs(base + (size_t)(t + 1) * 64);
        float4 b1 = __ldcs(base + (size_t)(t + 1) * 64 + 1);
        float d0 = a0.x*tga.x + a0.y*tga.y + a0.z*tga.z + a0.w*tga.w
                 + b0.x*tgb.x + b0.y*tgb.y + b0.z*tgb.z + b0.w*tgb.w;
        float d1 = a1.x*tga.x + a1.y*tga.y + a1.z*tga.z + a1.w*tga.w
                 + b1.x*tgb.x + b1.y*tgb.y + b1.z*tgb.z + b1.w*tgb.w;
#pragma unroll
        for (int off = 16; off; off >>= 1) {
            d0 += __shfl_xor_sync(0xffffffffu, d0, off);
            d1 += __shfl_xor_sync(0xffffffffu, d1, off);
        }
        float s0 = 1.f / (1.f + __expf(-d0));
        float s1 = 1.f / (1.f + __expf(-d1));
        accA.x += a0.x*s0 + a1.x*s1;
        accA.y += a0.y*s0 + a1.y*s1;
        accA.z += a0.z*s0 + a1.z*s1;
        accA.w += a0.w*s0 + a1.w*s1;
        accB.x += b0.x*s0 + b1.x*s1;
        accB.y += b0.y*s0 + b1.y*s1;
        accB.z += b0.z*s0 + b1.z*s1;
        accB.w += b0.w*s0 + b1.w*s1;
    }
    if (t < e) {
        float4 a0 = __ldcs(base + (size_t)t * 64);
        float4 b0 = __ldcs(base + (size_t)t * 64 + 1);
        float d0 = a0.x*tga.x + a0.y*tga.y + a0.z*tga.z + a0.w*tga.w
                 + b0.x*tgb.x + b0.y*tgb.y + b0.z*tgb.z + b0.w*tgb.w;
#pragma unroll
        for (int off = 16; off; off >>= 1)
            d0 += __shfl_xor_sync(0xffffffffu, d0, off);
        float s0 = 1.f / (1.f + __expf(-d0));
        accA.x += a0.x*s0; accA.y += a0.y*s0;
        accA.z += a0.z*s0; accA.w += a0.w*s0;
        accB.x += b0.x*s0; accB.y += b0.y*s0;
        accB.z += b0.z*s0; accB.w += b0.w*s0;
    }
    // Per-warp partial rows, then conflict-free column sum.
    *(float4*)&redw[w][lane * 8]     = accA;
    *(float4*)&redw[w][lane * 8 + 4] = accB;
    __syncthreads();
    float sum = 0.f;
#pragma unroll
    for (int j = 0; j < 8; ++j) sum += redw[j][tid];
    srep[tid] = sum;
    __syncthreads();

    int c = tid & 63;
    int r = tid >> 6;
    float4 rv = *(const float4*)&srep[c * 4];
    float4* ob = (float4*)out + c;
    for (int tt = s + r; tt < e; tt += 4)
        __stcs(ob + (size_t)tt * 64, rv);
}

extern "C" void kernel_launch(void* const* d_in, const int* in_sizes, int n_in,
                              void* d_out, int out_size) {
    const float* emb = (const float*)d_in[0];
    const float* W   = (const float*)d_in[1];
    const int*   obj = (const int*)d_in[2];
    float*       out = (float*)d_out;

    k_bounds<<<(T_TOK + 255) / 256, 256>>>(obj);
    k_segmean<<<N_SEG, 512>>>(emb);
    k_gemm_tanh<<<dim3(N_SEG / 128, D_DIM / 64), 256>>>(W);
    k_score_rep_bcast<<<N_SEG, 256>>>(emb, out);
}